// round 5
// baseline (speedup 1.0000x reference)
#include <cuda_runtime.h>
#include <math_constants.h>

#define BATCH 131072
#define NUM_CLASSES 1000
#define C4 250                 // float4 chunks per row (1000 floats)
#define MAIN_BLOCK 256
#define WARPS_PER_BLOCK (MAIN_BLOCK / 32)

__device__ int g_counts[NUM_CLASSES];
__device__ int g_hits[NUM_CLASSES];

// ---------------------------------------------------------------------------
// Kernel 1: zero the histograms (must re-zero every launch: deterministic,
// graph-replayable).
// ---------------------------------------------------------------------------
__global__ void zero_hist_kernel() {
    int i = blockIdx.x * blockDim.x + threadIdx.x;
    if (i < NUM_CLASSES) {
        g_counts[i] = 0;
        g_hits[i]   = 0;
    }
}

// ---------------------------------------------------------------------------
// Kernel 2: one warp per row. Dual argmax (pred & true) with first-index
// tie-break, then histogram atomics.
// ---------------------------------------------------------------------------
__global__ void __launch_bounds__(MAIN_BLOCK)
argmax_hist_kernel(const float4* __restrict__ y_pred,
                   const float4* __restrict__ y_true) {
    const int warp_id = (blockIdx.x * WARPS_PER_BLOCK) + (threadIdx.x >> 5);
    const int lane    = threadIdx.x & 31;
    if (warp_id >= BATCH) return;

    const float4* __restrict__ rp = y_pred + (size_t)warp_id * C4;
    const float4* __restrict__ rt = y_true + (size_t)warp_id * C4;

    float pbest = -CUDART_INF_F; int pidx = 0;
    float tbest = -CUDART_INF_F; int tidx = 0;

    // 8 strided float4 per lane per array; indices increase with k for a
    // fixed lane, so strict '>' keeps the first (smallest-index) max.
    #pragma unroll
    for (int k = 0; k < 8; k++) {
        const int i = k * 32 + lane;
        if (i < C4) {
            const float4 a = __ldg(rp + i);
            const float4 b = __ldg(rt + i);
            const int base = i * 4;
            if (a.x > pbest) { pbest = a.x; pidx = base + 0; }
            if (a.y > pbest) { pbest = a.y; pidx = base + 1; }
            if (a.z > pbest) { pbest = a.z; pidx = base + 2; }
            if (a.w > pbest) { pbest = a.w; pidx = base + 3; }
            if (b.x > tbest) { tbest = b.x; tidx = base + 0; }
            if (b.y > tbest) { tbest = b.y; tidx = base + 1; }
            if (b.z > tbest) { tbest = b.z; tidx = base + 2; }
            if (b.w > tbest) { tbest = b.w; tidx = base + 3; }
        }
    }

    // Warp argmax reduction, tie-break toward smaller index (jnp.argmax
    // returns the first occurrence).
    #pragma unroll
    for (int off = 16; off > 0; off >>= 1) {
        float pv = __shfl_down_sync(0xFFFFFFFFu, pbest, off);
        int   pi = __shfl_down_sync(0xFFFFFFFFu, pidx,  off);
        if (pv > pbest || (pv == pbest && pi < pidx)) { pbest = pv; pidx = pi; }
        float tv = __shfl_down_sync(0xFFFFFFFFu, tbest, off);
        int   ti = __shfl_down_sync(0xFFFFFFFFu, tidx,  off);
        if (tv > tbest || (tv == tbest && ti < tidx)) { tbest = tv; tidx = ti; }
    }

    if (lane == 0) {
        atomicAdd(&g_counts[tidx], 1);
        if (pidx == tidx) atomicAdd(&g_hits[tidx], 1);
    }
}

// ---------------------------------------------------------------------------
// Kernel 3: reduce 1000 classes -> -mean_recall (single block).
// ---------------------------------------------------------------------------
__global__ void __launch_bounds__(1024)
finalize_kernel(float* __restrict__ out) {
    __shared__ float s_rec[32];
    __shared__ float s_prs[32];

    const int tid = threadIdx.x;
    float rec_sum = 0.0f;
    float n_present = 0.0f;

    for (int c = tid; c < NUM_CLASSES; c += blockDim.x) {
        const int cnt = g_counts[c];
        if (cnt > 0) {
            n_present += 1.0f;
            rec_sum   += (float)g_hits[c] / (float)cnt;
        }
    }

    // warp reduce
    #pragma unroll
    for (int off = 16; off > 0; off >>= 1) {
        rec_sum   += __shfl_down_sync(0xFFFFFFFFu, rec_sum,   off);
        n_present += __shfl_down_sync(0xFFFFFFFFu, n_present, off);
    }
    const int warp = tid >> 5;
    const int lane = tid & 31;
    if (lane == 0) { s_rec[warp] = rec_sum; s_prs[warp] = n_present; }
    __syncthreads();

    if (warp == 0) {
        rec_sum   = (lane < 32) ? s_rec[lane] : 0.0f;
        n_present = (lane < 32) ? s_prs[lane] : 0.0f;
        #pragma unroll
        for (int off = 16; off > 0; off >>= 1) {
            rec_sum   += __shfl_down_sync(0xFFFFFFFFu, rec_sum,   off);
            n_present += __shfl_down_sync(0xFFFFFFFFu, n_present, off);
        }
        if (lane == 0) {
            out[0] = (n_present > 0.0f) ? -(rec_sum / n_present) : 0.0f;
        }
    }
}

// ---------------------------------------------------------------------------
extern "C" void kernel_launch(void* const* d_in, const int* in_sizes, int n_in,
                              void* d_out, int out_size) {
    const float4* y_pred = (const float4*)d_in[0];
    const float4* y_true = (const float4*)d_in[1];
    float* out = (float*)d_out;

    zero_hist_kernel<<<(NUM_CLASSES + 255) / 256, 256>>>();

    const int n_blocks = BATCH / WARPS_PER_BLOCK;   // 16384 blocks of 256
    argmax_hist_kernel<<<n_blocks, MAIN_BLOCK>>>(y_pred, y_true);

    finalize_kernel<<<1, 1024>>>(out);
}